// round 8
// baseline (speedup 1.0000x reference)
#include <cuda_runtime.h>
#include <cuda_bf16.h>

// Problem constants (WordSmoothCriterion: B=4, T=2048, V=32000, NNZ=801)
#define NROWS 8192
#define VDIM  32000
#define NNZ   801
#define TAU   0.8f
#define RARE  1.0f
#define ALPHA 0.7f

#define TPB    256
#define EPT    4      // 4*256 = 1024 >= 801 (k=3 slice predicated: tid < 33)
#define NB     16     // address buckets
#define BSHIFT 11     // bucket = col >> 11  (2048 cols = 8KB region)

// Scratch (device globals — allocation-free)
__device__ float g_smooth[NROWS];
__device__ float g_ml[NROWS];
__device__ float g_maskv[NROWS];
__device__ unsigned int g_count = 0;   // completion counter (self-resetting)

// ---------------------------------------------------------------------------
// Fused kernel: compute vals, bucket-sort (col,val) by 8KB region, gather in
// sorted order (DRAM row-buffer locality), reduce; last CTA finishes.
// ---------------------------------------------------------------------------
__global__ __launch_bounds__(TPB, 6)
void ws_fused_kernel(const float* __restrict__ logp,
                     const float* __restrict__ mask,
                     const float* __restrict__ sim_values,
                     const float* __restrict__ idf_values,
                     const int*   __restrict__ target,
                     const int*   __restrict__ sim_cols,
                     float*       __restrict__ out)
{
    const int n   = blockIdx.x;
    const int tid = threadIdx.x;
    const int r   = target[n];

    const float* __restrict__ sv = sim_values + (size_t)r * NNZ;
    const float* __restrict__ iv = idf_values + (size_t)r * NNZ;
    const int*   __restrict__ sc = sim_cols   + (size_t)r * NNZ;
    const float* __restrict__ lp = logp       + (size_t)n * VDIM;

    // Hoisted tail loads (overlap their latency with everything else)
    float m_early = 0.0f, lpr_early = 0.0f;
    if (tid == 0) { m_early = mask[n]; lpr_early = lp[r]; }

    const float inv_tau = 1.0f / TAU;
    const int warp = tid >> 5;
    const int lane = tid & 31;

    __shared__ unsigned short s_cnt[NB][TPB];  // counts -> per-thread prefix
    __shared__ int   s_base[NB];               // bucket totals -> bucket bases
    __shared__ int   s_col[NNZ];
    __shared__ float s_val[NNZ];
    __shared__ float s_rv[8], s_rgv[8];
    __shared__ bool  s_last;

    // ---- Phase A: load, compute val, count buckets ----
    #pragma unroll
    for (int b = 0; b < NB; b++) s_cnt[b][tid] = 0;

    int   c[EPT];
    int   bk[EPT];
    float vv[EPT];
    float sum_v = 0.0f;
    const bool p3 = (tid < NNZ - 3 * TPB);     // k=3 predicate (tid < 33)

    #pragma unroll
    for (int k = 0; k < EPT; k++) {
        const bool ok = (k < 3) || p3;
        const int  j  = tid + k * TPB;
        if (ok) {
            int   cc = sc[j];
            float s  = sv[j];
            float d  = iv[j];
            float val = __expf(__expf((s - 1.0f - TAU * RARE * d) * inv_tau) * inv_tau);
            c[k]  = cc;
            vv[k] = val;
            bk[k] = cc >> BSHIFT;
            sum_v += val;
            s_cnt[bk[k]][tid]++;               // same-thread RMW, no race
        } else {
            c[k] = 0; vv[k] = 0.0f; bk[k] = -1;
        }
    }
    __syncthreads();

    // ---- Phase B: per-bucket exclusive prefix over threads + bucket totals ----
    // warp w handles buckets 2w and 2w+1; lane owns 8 consecutive thread slots.
    #pragma unroll
    for (int bb = 0; bb < 2; bb++) {
        const int b = warp * 2 + bb;
        int v8[8], seg = 0;
        #pragma unroll
        for (int i = 0; i < 8; i++) { v8[i] = s_cnt[b][lane * 8 + i]; seg += v8[i]; }
        // warp-exclusive scan of segment sums
        int x = seg;
        #pragma unroll
        for (int o = 1; o < 32; o <<= 1) {
            int y = __shfl_up_sync(0xffffffffu, x, o);
            if (lane >= o) x += y;
        }
        int run = x - seg;                     // exclusive prefix for this lane
        #pragma unroll
        for (int i = 0; i < 8; i++) { int t = v8[i]; s_cnt[b][lane * 8 + i] = (unsigned short)run; run += t; }
        if (lane == 31) s_base[b] = run;       // bucket total
    }
    __syncthreads();

    // exclusive scan of the 16 bucket totals (warp 0)
    if (warp == 0) {
        int t = (lane < NB) ? s_base[lane] : 0;
        int x = t;
        #pragma unroll
        for (int o = 1; o < NB; o <<= 1) {
            int y = __shfl_up_sync(0xffffffffu, x, o);
            if (lane >= o) x += y;
        }
        if (lane < NB) s_base[lane] = x - t;
    }
    __syncthreads();

    // ---- Phase C: stable scatter into sorted order ----
    #pragma unroll
    for (int k = 0; k < EPT; k++) {
        const bool ok = (k < 3) || p3;
        if (ok) {
            int rank = 0;                      // stable rank among own elements
            #pragma unroll
            for (int kk = 0; kk < EPT; kk++)
                if (kk < k && bk[kk] == bk[k]) rank++;
            int pos = s_base[bk[k]] + (int)s_cnt[bk[k]][tid] + rank;
            s_col[pos] = c[k];
            s_val[pos] = vv[k];
        }
    }
    __syncthreads();

    // ---- Phase D: gather in sorted order (front-batched) ----
    int   cc2[EPT];
    float vl2[EPT];
    #pragma unroll
    for (int k = 0; k < EPT; k++) {
        const bool ok = (k < 3) || p3;
        const int  j  = tid + k * TPB;
        cc2[k] = ok ? s_col[j] : 0;
        vl2[k] = ok ? s_val[j] : 0.0f;
    }
    float g0 = lp[cc2[0]];
    float g1 = lp[cc2[1]];
    float g2 = lp[cc2[2]];
    float g3 = lp[cc2[3]];
    float sum_gv = (vl2[0] * g0 + vl2[1] * g1) + (vl2[2] * g2 + vl2[3] * g3);

    // -------- block reduction of (sum_v, sum_gv) --------
    #pragma unroll
    for (int o = 16; o > 0; o >>= 1) {
        sum_v  += __shfl_down_sync(0xffffffffu, sum_v,  o);
        sum_gv += __shfl_down_sync(0xffffffffu, sum_gv, o);
    }
    if (lane == 0) { s_rv[warp] = sum_v; s_rgv[warp] = sum_gv; }
    __syncthreads();
    if (warp == 0) {
        float a = (lane < 8) ? s_rv[lane]  : 0.0f;
        float b = (lane < 8) ? s_rgv[lane] : 0.0f;
        #pragma unroll
        for (int o = 4; o > 0; o >>= 1) {
            a += __shfl_down_sync(0xffffffffu, a, o);
            b += __shfl_down_sync(0xffffffffu, b, o);
        }
        if (lane == 0) {
            g_smooth[n] = b / a;
            g_ml[n]     = lpr_early * m_early;
            g_maskv[n]  = m_early;
            __threadfence();
            unsigned int old = atomicAdd(&g_count, 1u);
            s_last = (old == (unsigned int)(gridDim.x - 1));
        }
    }
    __syncthreads();

    // -------- last CTA: final deterministic reduction --------
    if (s_last) {
        double d_sm = 0.0, d_ml = 0.0, d_m = 0.0;
        for (int i = tid; i < NROWS; i += TPB) {
            d_sm += (double)g_smooth[i];
            d_ml += (double)g_ml[i];
            d_m  += (double)g_maskv[i];
        }
        #pragma unroll
        for (int o = 16; o > 0; o >>= 1) {
            d_sm += __shfl_down_sync(0xffffffffu, d_sm, o);
            d_ml += __shfl_down_sync(0xffffffffu, d_ml, o);
            d_m  += __shfl_down_sync(0xffffffffu, d_m,  o);
        }
        __shared__ double sh[3][8];
        if (lane == 0) { sh[0][warp] = d_sm; sh[1][warp] = d_ml; sh[2][warp] = d_m; }
        __syncthreads();
        if (warp == 0) {
            d_sm = (lane < 8) ? sh[0][lane] : 0.0;
            d_ml = (lane < 8) ? sh[1][lane] : 0.0;
            d_m  = (lane < 8) ? sh[2][lane] : 0.0;
            #pragma unroll
            for (int o = 4; o > 0; o >>= 1) {
                d_sm += __shfl_down_sync(0xffffffffu, d_sm, o);
                d_ml += __shfl_down_sync(0xffffffffu, d_ml, o);
                d_m  += __shfl_down_sync(0xffffffffu, d_m,  o);
            }
            if (lane == 0) {
                double smooth_loss = -d_sm / d_m;
                double ml_loss     = -d_ml / d_m;
                out[0] = (float)((double)ALPHA * smooth_loss
                                 + (1.0 - (double)ALPHA) * ml_loss);
                g_count = 0;   // reset for next graph replay
            }
        }
    }
}

// ---------------------------------------------------------------------------
extern "C" void kernel_launch(void* const* d_in, const int* in_sizes, int n_in,
                              void* d_out, int out_size)
{
    const float* logp       = (const float*)d_in[0];
    const float* mask       = (const float*)d_in[1];
    const float* sim_values = (const float*)d_in[2];
    const float* idf_values = (const float*)d_in[3];
    const int*   target     = (const int*)  d_in[4];
    const int*   sim_cols   = (const int*)  d_in[5];
    float*       out        = (float*)d_out;

    ws_fused_kernel<<<NROWS, TPB>>>(logp, mask, sim_values, idf_values,
                                    target, sim_cols, out);
}

// round 9
// speedup vs baseline: 1.1385x; 1.1385x over previous
#include <cuda_runtime.h>
#include <cuda_bf16.h>

// Problem constants (WordSmoothCriterion: B=4, T=2048, V=32000, NNZ=801)
#define NROWS 8192
#define VDIM  32000
#define NNZ   801
#define TAU   0.8f
#define RARE  1.0f
#define ALPHA 0.7f

#define TPB  256
#define EPT  4          // 4*256 = 1024 >= 801 (k=3 slice predicated: tid < 33)
#define GRID 592        // 148 SMs * 4 resident CTAs -> single persistent wave

// Scratch (device globals — allocation-free)
__device__ double g_psm[GRID];
__device__ double g_pml[GRID];
__device__ double g_pm[GRID];
__device__ unsigned int g_count = 0;   // completion counter (self-resetting)

// ---------------------------------------------------------------------------
// Persistent fused kernel: 592 CTAs, ~14 rows each, 1-row software pipeline.
// Next row's index/value loads and gathers are issued before the current
// row's reduction, keeping DRAM request issue continuous.
// ---------------------------------------------------------------------------
__global__ __launch_bounds__(TPB, 4)
void ws_persist_kernel(const float* __restrict__ logp,
                       const float* __restrict__ mask,
                       const float* __restrict__ sim_values,
                       const float* __restrict__ idf_values,
                       const int*   __restrict__ target,
                       const int*   __restrict__ sim_cols,
                       float*       __restrict__ out)
{
    const int bid  = blockIdx.x;
    const int tid  = threadIdx.x;
    const int warp = tid >> 5;
    const int lane = tid & 31;
    const float inv_tau = 1.0f / TAU;
    const bool p3 = (tid < NNZ - 3 * TPB);      // k=3 slice predicate (tid < 33)

    __shared__ float s_v[8], s_gv[8];
    __shared__ bool  s_last;

    // per-CTA accumulators (only thread 0 updates; fixed order -> deterministic)
    double acc_sm = 0.0, acc_ml = 0.0, acc_m = 0.0;

    // ---------------- prologue: load row n = bid ----------------
    int n = bid;
    const float* lpA = logp + (size_t)n * VDIM;
    {
    }
    int   cA[EPT];
    float sA[EPT], dA[EPT], gA[EPT];
    float mA = 0.0f, lprA = 0.0f;
    {
        const int rA = target[n];
        const float* svA = sim_values + (size_t)rA * NNZ;
        const float* ivA = idf_values + (size_t)rA * NNZ;
        const int*   scA = sim_cols   + (size_t)rA * NNZ;
        #pragma unroll
        for (int k = 0; k < EPT; k++) {
            const bool ok = (k < 3) || p3;
            const int  j  = tid + k * TPB;
            cA[k] = ok ? scA[j] : 0;
            sA[k] = ok ? svA[j] : 0.0f;
            dA[k] = ok ? ivA[j] : 0.0f;
        }
        if (tid == 0) { mA = mask[n]; lprA = lpA[rA]; }
        #pragma unroll
        for (int k = 0; k < EPT; k++) gA[k] = lpA[cA[k]];
    }

    // ---------------- main pipelined loop ----------------
    while (true) {
        const int  n2 = n + GRID;
        const bool hn = (n2 < NROWS);

        // ---- issue next row's index/value loads ----
        int   cB[EPT];
        float sB[EPT], dB[EPT];
        float mB = 0.0f, lprB = 0.0f;
        const float* lpB = logp;                 // safe default
        if (hn) {
            lpB = logp + (size_t)n2 * VDIM;
            const int rB = target[n2];
            const float* svB = sim_values + (size_t)rB * NNZ;
            const float* ivB = idf_values + (size_t)rB * NNZ;
            const int*   scB = sim_cols   + (size_t)rB * NNZ;
            #pragma unroll
            for (int k = 0; k < EPT; k++) {
                const bool ok = (k < 3) || p3;
                const int  j  = tid + k * TPB;
                cB[k] = ok ? scB[j] : 0;
                sB[k] = ok ? svB[j] : 0.0f;
                dB[k] = ok ? ivB[j] : 0.0f;
            }
            if (tid == 0) { mB = mask[n2]; lprB = lpB[rB]; }
        } else {
            #pragma unroll
            for (int k = 0; k < EPT; k++) { cB[k] = 0; sB[k] = 0.0f; dB[k] = 0.0f; }
        }

        // ---- compute current row ----
        float sum_v = 0.0f, sum_gv = 0.0f;
        #pragma unroll
        for (int k = 0; k < EPT; k++) {
            const bool ok = (k < 3) || p3;
            float val = __expf(__expf((sA[k] - 1.0f - TAU * RARE * dA[k]) * inv_tau) * inv_tau);
            if (!ok) val = 0.0f;
            sum_v  += val;
            sum_gv += val * gA[k];
        }

        // ---- issue next row's gathers (in flight during the reduction) ----
        float gB[EPT];
        if (hn) {
            #pragma unroll
            for (int k = 0; k < EPT; k++) gB[k] = lpB[cB[k]];
        } else {
            #pragma unroll
            for (int k = 0; k < EPT; k++) gB[k] = 0.0f;
        }

        // ---- block reduction of (sum_v, sum_gv) ----
        #pragma unroll
        for (int o = 16; o > 0; o >>= 1) {
            sum_v  += __shfl_down_sync(0xffffffffu, sum_v,  o);
            sum_gv += __shfl_down_sync(0xffffffffu, sum_gv, o);
        }
        if (lane == 0) { s_v[warp] = sum_v; s_gv[warp] = sum_gv; }
        __syncthreads();
        if (warp == 0) {
            float a = (lane < 8) ? s_v[lane]  : 0.0f;
            float b = (lane < 8) ? s_gv[lane] : 0.0f;
            #pragma unroll
            for (int o = 4; o > 0; o >>= 1) {
                a += __shfl_down_sync(0xffffffffu, a, o);
                b += __shfl_down_sync(0xffffffffu, b, o);
            }
            if (lane == 0) {
                acc_sm += (double)(b / a);
                acc_ml += (double)(lprA * mA);
                acc_m  += (double)mA;
            }
        }
        __syncthreads();                        // protect s_v/s_gv reuse

        if (!hn) break;

        // ---- rotate pipeline ----
        n   = n2;
        lpA = lpB; mA = mB; lprA = lprB;
        #pragma unroll
        for (int k = 0; k < EPT; k++) {
            cA[k] = cB[k]; sA[k] = sB[k]; dA[k] = dB[k]; gA[k] = gB[k];
        }
    }

    // ---------------- write per-CTA partials, last CTA finishes ----------------
    if (tid == 0) {
        g_psm[bid] = acc_sm;
        g_pml[bid] = acc_ml;
        g_pm[bid]  = acc_m;
        __threadfence();
        unsigned int old = atomicAdd(&g_count, 1u);
        s_last = (old == (unsigned int)(GRID - 1));
    }
    __syncthreads();

    if (s_last) {
        double d_sm = 0.0, d_ml = 0.0, d_m = 0.0;
        for (int i = tid; i < GRID; i += TPB) {   // fixed order -> deterministic
            d_sm += g_psm[i];
            d_ml += g_pml[i];
            d_m  += g_pm[i];
        }
        #pragma unroll
        for (int o = 16; o > 0; o >>= 1) {
            d_sm += __shfl_down_sync(0xffffffffu, d_sm, o);
            d_ml += __shfl_down_sync(0xffffffffu, d_ml, o);
            d_m  += __shfl_down_sync(0xffffffffu, d_m,  o);
        }
        __shared__ double sh[3][8];
        if (lane == 0) { sh[0][warp] = d_sm; sh[1][warp] = d_ml; sh[2][warp] = d_m; }
        __syncthreads();
        if (warp == 0) {
            d_sm = (lane < 8) ? sh[0][lane] : 0.0;
            d_ml = (lane < 8) ? sh[1][lane] : 0.0;
            d_m  = (lane < 8) ? sh[2][lane] : 0.0;
            #pragma unroll
            for (int o = 4; o > 0; o >>= 1) {
                d_sm += __shfl_down_sync(0xffffffffu, d_sm, o);
                d_ml += __shfl_down_sync(0xffffffffu, d_ml, o);
                d_m  += __shfl_down_sync(0xffffffffu, d_m,  o);
            }
            if (lane == 0) {
                double smooth_loss = -d_sm / d_m;
                double ml_loss     = -d_ml / d_m;
                out[0] = (float)((double)ALPHA * smooth_loss
                                 + (1.0 - (double)ALPHA) * ml_loss);
                g_count = 0;   // reset for next graph replay
            }
        }
    }
}

// ---------------------------------------------------------------------------
extern "C" void kernel_launch(void* const* d_in, const int* in_sizes, int n_in,
                              void* d_out, int out_size)
{
    const float* logp       = (const float*)d_in[0];
    const float* mask       = (const float*)d_in[1];
    const float* sim_values = (const float*)d_in[2];
    const float* idf_values = (const float*)d_in[3];
    const int*   target     = (const int*)  d_in[4];
    const int*   sim_cols   = (const int*)  d_in[5];
    float*       out        = (float*)d_out;

    ws_persist_kernel<<<GRID, TPB>>>(logp, mask, sim_values, idf_values,
                                     target, sim_cols, out);
}